// round 13
// baseline (speedup 1.0000x reference)
#include <cuda_runtime.h>
#include <stdint.h>

#define N_NODES 100000
#define E_EDGES 1600000
#define HID 64
#define SCAN_B 512

// ---------------- scratch (no allocation allowed) ----------------
__device__ float g_bufA[N_NODES * HID];        // dinv-scaled GEMM out
__device__ float g_bufB[N_NODES * HID];        // layer output h
__device__ float g_dinv[N_NODES];
__device__ int   g_cnt[N_NODES];               // per-dst edge counts
__device__ int   g_off[N_NODES + 1];           // CSR offsets
__device__ int   g_cur[N_NODES];               // fill cursors (init from off)
__device__ int   g_bsum[(N_NODES + SCAN_B - 1) / SCAN_B];
__device__ __align__(16) int g_csr[E_EDGES];   // src indices sorted by dst
__device__ int   g_is64;                       // 1 if edge_index is int64

__device__ __forceinline__ float lrelu1(float v) {
    return fmaxf(v, 0.f) + 0.01f * fminf(v, 0.f);
}

// ---------------- dtype detect (block 0) + zero cnt (blocks 1..) ----------
__global__ void k_detect_zero(const unsigned int* __restrict__ u32buf,
                              int* __restrict__ cnt, int n) {
    if (blockIdx.x == 0) {
        __shared__ unsigned int s_or[256];
        unsigned int acc = 0;
        for (int i = threadIdx.x; i < 2048; i += 256)
            acc |= u32buf[2 * i + 1];          // hi word of candidate int64 #i
        s_or[threadIdx.x] = acc;
        __syncthreads();
        for (int s = 128; s > 0; s >>= 1) {
            if (threadIdx.x < s) s_or[threadIdx.x] |= s_or[threadIdx.x + s];
            __syncthreads();
        }
        if (threadIdx.x == 0) g_is64 = (s_or[0] == 0) ? 1 : 0;
    } else {
        int i = (blockIdx.x - 1) * blockDim.x + threadIdx.x;
        if (i < n) cnt[i] = 0;
    }
}

__device__ __forceinline__ int load_idx(const unsigned int* u32buf, long long elem, int is64, int n) {
    unsigned int v = is64 ? u32buf[2 * elem] : u32buf[elem];
    int iv = (int)v;
    return min(max(iv, 0), n - 1);
}

// ---------------- graph precompute ----------------
__global__ void k_count(const unsigned int* __restrict__ ei, int* __restrict__ cnt,
                        int E, int n) {
    int e = blockIdx.x * blockDim.x + threadIdx.x;
    if (e < E) {
        int is64 = g_is64;
        int d = load_idx(ei, (long long)E + e, is64, n);
        atomicAdd(cnt + d, 1);
    }
}

// ---------------- scan over cnt -> off, fused dinv ----------------
__global__ void k_scan_block(const int* __restrict__ cnt, int* __restrict__ off,
                             int* __restrict__ bsum, float* __restrict__ dinv, int n) {
    __shared__ int s[SCAN_B];
    int i = blockIdx.x * SCAN_B + threadIdx.x;
    int v = (i < n) ? cnt[i] : 0;
    if (i < n) dinv[i] = rsqrtf(1.0f + (float)v);       // +1 self loop (fused)
    s[threadIdx.x] = v;
    __syncthreads();
#pragma unroll
    for (int d = 1; d < SCAN_B; d <<= 1) {
        int t = (threadIdx.x >= d) ? s[threadIdx.x - d] : 0;
        __syncthreads();
        s[threadIdx.x] += t;
        __syncthreads();
    }
    if (i < n) off[i] = s[threadIdx.x] - v;             // exclusive within block
    if (threadIdx.x == SCAN_B - 1) bsum[blockIdx.x] = s[SCAN_B - 1];
}

__global__ void k_scan_bsum(int* __restrict__ bsum, int nb) {   // nb <= SCAN_B
    __shared__ int s[SCAN_B];
    int v = (threadIdx.x < nb) ? bsum[threadIdx.x] : 0;
    s[threadIdx.x] = v;
    __syncthreads();
#pragma unroll
    for (int d = 1; d < SCAN_B; d <<= 1) {
        int t = (threadIdx.x >= d) ? s[threadIdx.x - d] : 0;
        __syncthreads();
        s[threadIdx.x] += t;
        __syncthreads();
    }
    if (threadIdx.x < nb) bsum[threadIdx.x] = s[threadIdx.x] - v;   // exclusive
}

__global__ void k_scan_add(int* __restrict__ off, int* __restrict__ cur,
                           const int* __restrict__ bsum, int n, int E) {
    int i = blockIdx.x * blockDim.x + threadIdx.x;
    if (i < n) {
        int o = off[i] + bsum[i / SCAN_B];
        off[i] = o;
        cur[i] = o;
    }
    if (i == 0) off[n] = E;
}

// ---------------- CSR fill (src index only; no norms) ----------------
__global__ void k_fill(const unsigned int* __restrict__ ei,
                       int* __restrict__ cur, int* __restrict__ csr, int E, int n) {
    int e = blockIdx.x * blockDim.x + threadIdx.x;
    if (e < E) {
        int is64 = g_is64;
        int s = load_idx(ei, e, is64, n);
        int d = load_idx(ei, (long long)E + e, is64, n);
        int pos = atomicAdd(cur + d, 1);
        csr[pos] = s;
    }
}

// ---------------- GEMM: out[n,64] = dinv[row] * (in[n,64] @ W[64,64]) ------
// (R11 row-per-thread body + dinv epilogue scale — frozen)
__global__ __launch_bounds__(128)
void k_gemm64(const float* __restrict__ in, const float* __restrict__ W,
              const float* __restrict__ dinvv, float* __restrict__ out, int n) {
    __shared__ float Ws[64 * 64];
    for (int i = threadIdx.x; i < 64 * 16; i += blockDim.x)
        ((float4*)Ws)[i] = ((const float4*)W)[i];
    __syncthreads();

    int row = blockIdx.x * blockDim.x + threadIdx.x;
    if (row >= n) return;

    float acc[64];
#pragma unroll
    for (int j = 0; j < 64; j++) acc[j] = 0.f;

    const float4* inr = (const float4*)(in + (size_t)row * HID);

#pragma unroll 4
    for (int k4 = 0; k4 < 16; k4++) {
        float4 v = inr[k4];
        float av[4] = {v.x, v.y, v.z, v.w};
#pragma unroll
        for (int kk = 0; kk < 4; kk++) {
            const float* wrow = Ws + (k4 * 4 + kk) * 64;
#pragma unroll
            for (int j = 0; j < 64; j++)
                acc[j] = fmaf(av[kk], wrow[j], acc[j]);
        }
    }

    float di = __ldg(dinvv + row);
    float4* outr = (float4*)(out + (size_t)row * HID);
#pragma unroll
    for (int j = 0; j < 16; j++)
        outr[j] = make_float4(di * acc[4 * j], di * acc[4 * j + 1],
                              di * acc[4 * j + 2], di * acc[4 * j + 3]);
}

// ---------------- gather: h[node] = lrelu(dinv[node]*(bufA[node]
//                                    + sum_e bufA[src_e]) + bias) ----------
// One warp per node. 2 edges per iteration: lanes 0-15 fetch the even edge's
// row, lanes 16-31 the odd edge's row (one LDG.128 for both); csr pair read
// as one int2 broadcast. Halves combined via shfl_xor(16) at the end.
__global__ __launch_bounds__(256)
void k_gather(const float* __restrict__ lin, const int* __restrict__ csr,
              const int* __restrict__ off, const float* __restrict__ dinv,
              const float* __restrict__ bias, float* __restrict__ outp, int n) {
    int warp = (blockIdx.x * blockDim.x + threadIdx.x) >> 5;
    int lane = threadIdx.x & 31;
    if (warp >= n) return;
    int node = warp;

    int beg = __ldg(off + node);
    int end = __ldg(off + node + 1);

    int half  = lane >> 4;          // 0: even edge of pair, 1: odd edge
    int qlane = lane & 15;          // owns cols [4*qlane, 4*qlane+4)

    const float4* lin4 = (const float4*)lin;

    // self term (pre-scaled by dinv in GEMM epilogue) — half 0 only
    float4 acc = make_float4(0.f, 0.f, 0.f, 0.f);
    if (half == 0) acc = __ldg(lin4 + (size_t)node * 16 + qlane);

    int i = beg;
    // peel head to even index so int2 loads are 8B-aligned
    if (i < end && (i & 1)) {
        if (half == 0) {
            int s = __ldg(csr + i);
            float4 v = __ldg(lin4 + (size_t)s * 16 + qlane);
            acc.x += v.x; acc.y += v.y; acc.z += v.z; acc.w += v.w;
        }
        i++;
    }
    for (; i + 2 <= end; i += 2) {
        int2 pr = __ldg((const int2*)(csr + i));
        int s = half ? pr.y : pr.x;
        float4 v = __ldg(lin4 + (size_t)s * 16 + qlane);
        acc.x += v.x; acc.y += v.y; acc.z += v.z; acc.w += v.w;
    }
    if (i < end) {
        if (half == 0) {
            int s = __ldg(csr + i);
            float4 v = __ldg(lin4 + (size_t)s * 16 + qlane);
            acc.x += v.x; acc.y += v.y; acc.z += v.z; acc.w += v.w;
        }
    }

    // combine halves
    acc.x += __shfl_xor_sync(0xFFFFFFFFu, acc.x, 16);
    acc.y += __shfl_xor_sync(0xFFFFFFFFu, acc.y, 16);
    acc.z += __shfl_xor_sync(0xFFFFFFFFu, acc.z, 16);
    acc.w += __shfl_xor_sync(0xFFFFFFFFu, acc.w, 16);

    if (half == 0) {
        float di = __ldg(dinv + node);
        float4 b = __ldg(((const float4*)bias) + qlane);
        float4 o;
        o.x = lrelu1(fmaf(di, acc.x, b.x));
        o.y = lrelu1(fmaf(di, acc.y, b.y));
        o.z = lrelu1(fmaf(di, acc.z, b.z));
        o.w = lrelu1(fmaf(di, acc.w, b.w));
        ((float4*)outp)[(size_t)node * 16 + qlane] = o;
    }
}

// ---------------- launch ----------------
extern "C" void kernel_launch(void* const* d_in, const int* in_sizes, int n_in,
                              void* d_out, int out_size) {
    const float*        x  = (const float*)d_in[0];
    const unsigned int* ei = (const unsigned int*)d_in[1];
    const float*        W1 = (const float*)d_in[2];
    const float*        b1 = (const float*)d_in[3];
    const float*        W2 = (const float*)d_in[4];
    const float*        b2 = (const float*)d_in[5];
    const float*        W3 = (const float*)d_in[6];
    const float*        b3 = (const float*)d_in[7];
    float* out = (float*)d_out;

    const int n = in_sizes[0] / HID;        // 100000
    const int E = in_sizes[1] / 2;          // 1600000

    float* bufA;  cudaGetSymbolAddress((void**)&bufA, g_bufA);
    float* bufB;  cudaGetSymbolAddress((void**)&bufB, g_bufB);
    float* dinv;  cudaGetSymbolAddress((void**)&dinv, g_dinv);
    int*   cnt;   cudaGetSymbolAddress((void**)&cnt,  g_cnt);
    int*   off;   cudaGetSymbolAddress((void**)&off,  g_off);
    int*   cur;   cudaGetSymbolAddress((void**)&cur,  g_cur);
    int*   bsum;  cudaGetSymbolAddress((void**)&bsum, g_bsum);
    int*   csr;   cudaGetSymbolAddress((void**)&csr,  g_csr);

    const int T = 256;
    int gn  = (n + T - 1) / T;
    int gE  = (E + T - 1) / T;
    int nb  = (n + SCAN_B - 1) / SCAN_B;     // 196
    int gRow = (n + 127) / 128;              // row per thread
    int gGat = (n * 32 + T - 1) / T;         // warp per node

    // dtype detection + CSR build
    k_detect_zero<<<1 + gn, T>>>(ei, cnt, n);
    k_count<<<gE, T>>>(ei, cnt, E, n);
    k_scan_block<<<nb, SCAN_B>>>(cnt, off, bsum, dinv, n);
    k_scan_bsum<<<1, SCAN_B>>>(bsum, nb);
    k_scan_add<<<gn, T>>>(off, cur, bsum, n, E);
    k_fill<<<gE, T>>>(ei, cur, csr, E, n);

    // layer 1
    k_gemm64<<<gRow, 128>>>(x, W1, dinv, bufA, n);
    k_gather<<<gGat, T>>>(bufA, csr, off, dinv, b1, bufB, n);
    // layer 2
    k_gemm64<<<gRow, 128>>>(bufB, W2, dinv, bufA, n);
    k_gather<<<gGat, T>>>(bufA, csr, off, dinv, b2, bufB, n);
    // layer 3 -> d_out directly (plain stores only)
    k_gemm64<<<gRow, 128>>>(bufB, W3, dinv, bufA, n);
    k_gather<<<gGat, T>>>(bufA, csr, off, dinv, b3, out, n);
}

// round 14
// speedup vs baseline: 1.5196x; 1.5196x over previous
#include <cuda_runtime.h>
#include <stdint.h>

#define N_NODES 100000
#define E_EDGES 1600000
#define HID 64

// ---------------- scratch (no allocation allowed) ----------------
__device__ float g_bufA[N_NODES * HID];        // dinv-scaled GEMM out
__device__ float g_bufB[N_NODES * HID];        // layer output h
__device__ float g_dinv[N_NODES];
__device__ int   g_cnt[N_NODES];               // per-dst edge counts
__device__ int   g_off[N_NODES];               // CSR range starts (unordered alloc)
__device__ int   g_cur[N_NODES];               // fill cursors (init from off)
__device__ int   g_csr[E_EDGES];               // src indices grouped by dst
__device__ unsigned int g_total;               // bump allocator
__device__ int   g_is64;                       // 1 if edge_index is int64

__device__ __forceinline__ float lrelu1(float v) {
    return fmaxf(v, 0.f) + 0.01f * fminf(v, 0.f);
}

// ---------------- dtype detect (block 0) + zero cnt (blocks 1..) ----------
__global__ void k_detect_zero(const unsigned int* __restrict__ u32buf,
                              int* __restrict__ cnt, int n) {
    if (blockIdx.x == 0) {
        __shared__ unsigned int s_or[256];
        unsigned int acc = 0;
        for (int i = threadIdx.x; i < 2048; i += 256)
            acc |= u32buf[2 * i + 1];          // hi word of candidate int64 #i
        s_or[threadIdx.x] = acc;
        __syncthreads();
        for (int s = 128; s > 0; s >>= 1) {
            if (threadIdx.x < s) s_or[threadIdx.x] |= s_or[threadIdx.x + s];
            __syncthreads();
        }
        if (threadIdx.x == 0) {
            g_is64 = (s_or[0] == 0) ? 1 : 0;
            g_total = 0u;                      // reset bump allocator
        }
    } else {
        int i = (blockIdx.x - 1) * blockDim.x + threadIdx.x;
        if (i < n) cnt[i] = 0;
    }
}

__device__ __forceinline__ int load_idx(const unsigned int* u32buf, long long elem, int is64, int n) {
    unsigned int v = is64 ? u32buf[2 * elem] : u32buf[elem];
    int iv = (int)v;
    return min(max(iv, 0), n - 1);
}

// ---------------- count in-degrees ----------------
__global__ void k_count(const unsigned int* __restrict__ ei, int* __restrict__ cnt,
                        int E, int n) {
    int e = blockIdx.x * blockDim.x + threadIdx.x;
    if (e < E) {
        int is64 = g_is64;
        int d = load_idx(ei, (long long)E + e, is64, n);
        atomicAdd(cnt + d, 1);
    }
}

// ---------------- allocate CSR ranges (order-free bump alloc) + dinv -------
__global__ void k_alloc(const int* __restrict__ cnt, int* __restrict__ off,
                        int* __restrict__ cur, float* __restrict__ dinv, int n) {
    int i = blockIdx.x * blockDim.x + threadIdx.x;
    if (i < n) {
        int c = cnt[i];
        dinv[i] = rsqrtf(1.0f + (float)c);              // +1 self loop
        int o = (int)atomicAdd(&g_total, (unsigned int)c);   // warp-aggregated
        off[i] = o;
        cur[i] = o;
    }
}

// ---------------- CSR fill (src index only) ----------------
__global__ void k_fill(const unsigned int* __restrict__ ei,
                       int* __restrict__ cur, int* __restrict__ csr, int E, int n) {
    int e = blockIdx.x * blockDim.x + threadIdx.x;
    if (e < E) {
        int is64 = g_is64;
        int s = load_idx(ei, e, is64, n);
        int d = load_idx(ei, (long long)E + e, is64, n);
        int pos = atomicAdd(cur + d, 1);
        csr[pos] = s;
    }
}

// ---------------- GEMM: out[n,64] = dinv[row] * (in[n,64] @ W[64,64]) ------
// (R11 row-per-thread body — frozen)
__global__ __launch_bounds__(128)
void k_gemm64(const float* __restrict__ in, const float* __restrict__ W,
              const float* __restrict__ dinvv, float* __restrict__ out, int n) {
    __shared__ float Ws[64 * 64];
    for (int i = threadIdx.x; i < 64 * 16; i += blockDim.x)
        ((float4*)Ws)[i] = ((const float4*)W)[i];
    __syncthreads();

    int row = blockIdx.x * blockDim.x + threadIdx.x;
    if (row >= n) return;

    float acc[64];
#pragma unroll
    for (int j = 0; j < 64; j++) acc[j] = 0.f;

    const float4* inr = (const float4*)(in + (size_t)row * HID);

#pragma unroll 4
    for (int k4 = 0; k4 < 16; k4++) {
        float4 v = inr[k4];
        float av[4] = {v.x, v.y, v.z, v.w};
#pragma unroll
        for (int kk = 0; kk < 4; kk++) {
            const float* wrow = Ws + (k4 * 4 + kk) * 64;
#pragma unroll
            for (int j = 0; j < 64; j++)
                acc[j] = fmaf(av[kk], wrow[j], acc[j]);
        }
    }

    float di = __ldg(dinvv + row);
    float4* outr = (float4*)(out + (size_t)row * HID);
#pragma unroll
    for (int j = 0; j < 16; j++)
        outr[j] = make_float4(di * acc[4 * j], di * acc[4 * j + 1],
                              di * acc[4 * j + 2], di * acc[4 * j + 3]);
}

// ---------------- gather: h[node] = lrelu(dinv[node]*(bufA[node]
//                                    + sum_e bufA[src_e]) + bias) ----------
// One warp per node; lane owns 2 feature columns. (R11 body — frozen;
// range end now beg + cnt[node] since offsets are unordered.)
__global__ __launch_bounds__(256)
void k_gather(const float* __restrict__ lin, const int* __restrict__ csr,
              const int* __restrict__ off, const int* __restrict__ cnt,
              const float* __restrict__ dinv,
              const float* __restrict__ bias, float* __restrict__ outp, int n) {
    int warp = (blockIdx.x * blockDim.x + threadIdx.x) >> 5;
    int lane = threadIdx.x & 31;
    if (warp >= n) return;
    int node = warp;

    int beg = __ldg(off + node);
    int end = beg + __ldg(cnt + node);

    const float2* lin2 = (const float2*)lin;
    float2 t = __ldg(lin2 + (size_t)node * 32 + lane);   // self term (pre-scaled)
    float tx = t.x, ty = t.y;

    int i = beg;
    for (; i + 2 <= end; i += 2) {
        int s0 = __ldg(csr + i);
        int s1 = __ldg(csr + i + 1);
        float2 v0 = __ldg(lin2 + (size_t)s0 * 32 + lane);
        float2 v1 = __ldg(lin2 + (size_t)s1 * 32 + lane);
        tx += v0.x; ty += v0.y;
        tx += v1.x; ty += v1.y;
    }
    if (i < end) {
        int s0 = __ldg(csr + i);
        float2 v0 = __ldg(lin2 + (size_t)s0 * 32 + lane);
        tx += v0.x; ty += v0.y;
    }

    float di = __ldg(dinv + node);
    float2 b = __ldg(((const float2*)bias) + lane);
    float2 o;
    o.x = lrelu1(fmaf(di, tx, b.x));
    o.y = lrelu1(fmaf(di, ty, b.y));
    ((float2*)outp)[(size_t)node * 32 + lane] = o;
}

// ---------------- launch ----------------
extern "C" void kernel_launch(void* const* d_in, const int* in_sizes, int n_in,
                              void* d_out, int out_size) {
    const float*        x  = (const float*)d_in[0];
    const unsigned int* ei = (const unsigned int*)d_in[1];
    const float*        W1 = (const float*)d_in[2];
    const float*        b1 = (const float*)d_in[3];
    const float*        W2 = (const float*)d_in[4];
    const float*        b2 = (const float*)d_in[5];
    const float*        W3 = (const float*)d_in[6];
    const float*        b3 = (const float*)d_in[7];
    float* out = (float*)d_out;

    const int n = in_sizes[0] / HID;        // 100000
    const int E = in_sizes[1] / 2;          // 1600000

    float* bufA;  cudaGetSymbolAddress((void**)&bufA, g_bufA);
    float* bufB;  cudaGetSymbolAddress((void**)&bufB, g_bufB);
    float* dinv;  cudaGetSymbolAddress((void**)&dinv, g_dinv);
    int*   cnt;   cudaGetSymbolAddress((void**)&cnt,  g_cnt);
    int*   off;   cudaGetSymbolAddress((void**)&off,  g_off);
    int*   cur;   cudaGetSymbolAddress((void**)&cur,  g_cur);
    int*   csr;   cudaGetSymbolAddress((void**)&csr,  g_csr);

    const int T = 256;
    int gn  = (n + T - 1) / T;
    int gE  = (E + T - 1) / T;
    int gRow = (n + 127) / 128;              // row per thread
    int gGat = (n * 32 + T - 1) / T;         // warp per node

    // dtype detection + CSR build (4 kernels)
    k_detect_zero<<<1 + gn, T>>>(ei, cnt, n);
    k_count<<<gE, T>>>(ei, cnt, E, n);
    k_alloc<<<gn, T>>>(cnt, off, cur, dinv, n);
    k_fill<<<gE, T>>>(ei, cur, csr, E, n);

    // layer 1
    k_gemm64<<<gRow, 128>>>(x, W1, dinv, bufA, n);
    k_gather<<<gGat, T>>>(bufA, csr, off, cnt, dinv, b1, bufB, n);
    // layer 2
    k_gemm64<<<gRow, 128>>>(bufB, W2, dinv, bufA, n);
    k_gather<<<gGat, T>>>(bufA, csr, off, cnt, dinv, b2, bufB, n);
    // layer 3 -> d_out directly (plain stores only)
    k_gemm64<<<gRow, 128>>>(bufB, W3, dinv, bufA, n);
    k_gather<<<gGat, T>>>(bufA, csr, off, cnt, dinv, b3, out, n);
}